// round 12
// baseline (speedup 1.0000x reference)
#include <cuda_runtime.h>
#include <stdint.h>
#include <math.h>

#define BB 32
#define TXX 384
#define TYY 1536
#define DIMK 256
#define NF 80
#define NEGF (-1000000000.0f)
#define CONSTF (-73.51508265637381f)   /* -0.5*log(2*pi)*80 */

#define ATTN_SZ ((size_t)BB * TXX * TYY)

// DP ring: 32 rows = 4 blocks of 8 rows
#define DSLOT 32
#define BLK_BYTES (8 * TXX * 4)   /* 12288 */
#define RING_BYTES (DSLOT * TXX * 4)              /* 49152 */
#define SDEC_OFF  RING_BYTES                      /* uint8[TYY+8][64] */
#define CARRY_OFF (SDEC_OFF + (TYY + 8) * 64)     /* float[4] */
#define MBAR_OFF  (CARRY_OFF + 16)
#define DP_SMEM   (MBAR_OFF + 48)

// ---------------- scratch (static device memory; no allocation) -------------
__device__ float g_xp[(size_t)BB * NF * TXX];          // [b][f][t]
__device__ float g_xsq[BB * TXX];
__device__ float g_ysq[BB * TYY];
__device__ float g_v[(size_t)BB * TYY * TXX];          // [b][y][t]
__device__ int   g_idx[BB * TYY];
__device__ float g_dur[BB * TXX];

// ---------------------------------------------------------------------------
// y_square[b][s] = -0.5 * sum_f y[b][f][s]^2
__global__ void ysq_kernel(const float* __restrict__ y) {
    int b = blockIdx.y;
    int s = blockIdx.x * 256 + threadIdx.x;
    if (s >= TYY) return;
    const float* yb = y + (size_t)b * NF * TYY + s;
    float sum = 0.f;
#pragma unroll
    for (int f = 0; f < NF; ++f) {
        float v = yb[(size_t)f * TYY];
        sum += v * v;
    }
    g_ysq[b * TYY + s] = -0.5f * sum;
}

// ---------------------------------------------------------------------------
// xp[b][f][t] = sum_d x[b][t][d] * W[f][d] + bias[f];  xsq[b][t] = -0.5*sum_f xp^2
__global__ __launch_bounds__(160) void xp_kernel(const float* __restrict__ x,
                                                 const float* __restrict__ W,
                                                 const float* __restrict__ bias) {
    __shared__ float xs[32][128];   // [k][t]
    __shared__ float ws[32][80];    // [k][f]
    __shared__ float part[10][128];

    int b  = blockIdx.y;
    int t0 = blockIdx.x * 128;
    int tid = threadIdx.x;
    int tx = tid & 15;        // t-group
    int fg = tid >> 4;        // f-group (0..9)

    float acc[8][8];
#pragma unroll
    for (int i = 0; i < 8; ++i)
#pragma unroll
        for (int j = 0; j < 8; ++j) acc[i][j] = 0.f;

    const float* xb = x + ((size_t)b * TXX + t0) * DIMK;

    for (int k0 = 0; k0 < DIMK; k0 += 32) {
        for (int i = tid; i < 1024; i += 160) {     // 128 t x 8 float4
            int t = i >> 3, kq = i & 7;
            float4 v = *(const float4*)(xb + (size_t)t * DIMK + k0 + kq * 4);
            xs[kq * 4 + 0][t] = v.x; xs[kq * 4 + 1][t] = v.y;
            xs[kq * 4 + 2][t] = v.z; xs[kq * 4 + 3][t] = v.w;
        }
        for (int i = tid; i < 640; i += 160) {      // 80 f x 8 float4
            int f = i >> 3, kq = i & 7;
            float4 v = *(const float4*)(W + (size_t)f * DIMK + k0 + kq * 4);
            ws[kq * 4 + 0][f] = v.x; ws[kq * 4 + 1][f] = v.y;
            ws[kq * 4 + 2][f] = v.z; ws[kq * 4 + 3][f] = v.w;
        }
        __syncthreads();
#pragma unroll 8
        for (int kk = 0; kk < 32; ++kk) {
            float4 xa = *(const float4*)&xs[kk][tx * 8];
            float4 xb4 = *(const float4*)&xs[kk][tx * 8 + 4];
            float4 wa = *(const float4*)&ws[kk][fg * 8];
            float4 wb4 = *(const float4*)&ws[kk][fg * 8 + 4];
            float xv[8] = {xa.x, xa.y, xa.z, xa.w, xb4.x, xb4.y, xb4.z, xb4.w};
            float wv[8] = {wa.x, wa.y, wa.z, wa.w, wb4.x, wb4.y, wb4.z, wb4.w};
#pragma unroll
            for (int i = 0; i < 8; ++i)
#pragma unroll
                for (int j = 0; j < 8; ++j) acc[i][j] += xv[i] * wv[j];
        }
        __syncthreads();
    }

    float bv[8];
#pragma unroll
    for (int j = 0; j < 8; ++j) bv[j] = bias[fg * 8 + j];

    float ss[8];
#pragma unroll
    for (int i = 0; i < 8; ++i) ss[i] = 0.f;

#pragma unroll
    for (int i = 0; i < 8; ++i) {
        int t = t0 + tx * 8 + i;
#pragma unroll
        for (int j = 0; j < 8; ++j) {
            float v = acc[i][j] + bv[j];
            g_xp[((size_t)b * NF + fg * 8 + j) * TXX + t] = v;
            ss[i] += v * v;
        }
    }
#pragma unroll
    for (int i = 0; i < 8; ++i) part[fg][tx * 8 + i] = ss[i];
    __syncthreads();
    if (tid < 128) {
        float s = 0.f;
#pragma unroll
        for (int g = 0; g < 10; ++g) s += part[g][tid];
        g_xsq[b * TXX + t0 + tid] = -0.5f * s;
    }
}

// ---------------------------------------------------------------------------
// v[b][y][t] = ysq[y] + sum_f xp[b][f][t]*y[b][f][y] + xsq[t] + CONST  (masked)
// Packed f32x2 FMA inner loop.  Tiles with t0 >= xlen or t0 > y0+128 skipped.
__global__ __launch_bounds__(256) void cross_kernel(const float* __restrict__ y,
                                                    const int* __restrict__ xl,
                                                    const int* __restrict__ yl) {
    extern __shared__ float sm[];
    float* Ys = sm;            // [80][128]
    float* Xs = sm + 80 * 128; // [80][128]

    int b  = blockIdx.z;
    int y0 = blockIdx.y * 128;
    int t0 = blockIdx.x * 128;
    int ylen = yl[b], xlen = xl[b];
    if (y0 >= ylen) return;
    if (t0 >= xlen) return;
    if (t0 > y0 + 128) return;

    int tid = threadIdx.x;

    const float* yb = y + (size_t)b * NF * TYY;
    for (int i = tid; i < 2560; i += 256) {
        int f = i >> 5, q = i & 31;
        *(float4*)&Ys[f * 128 + q * 4] =
            *(const float4*)(yb + (size_t)f * TYY + y0 + q * 4);
    }
    const float* xpb = g_xp + (size_t)b * NF * TXX;
    for (int i = tid; i < 2560; i += 256) {
        int f = i >> 5, q = i & 31;
        *(float4*)&Xs[f * 128 + q * 4] =
            *(const float4*)(xpb + (size_t)f * TXX + t0 + q * 4);
    }
    __syncthreads();

    int tx = tid & 15;   // t
    int ty = tid >> 4;   // y

    unsigned long long acc2[8][4];
#pragma unroll
    for (int i = 0; i < 8; ++i)
#pragma unroll
        for (int j = 0; j < 4; ++j) acc2[i][j] = 0ull;

#pragma unroll 4
    for (int f = 0; f < NF; ++f) {
        float4 ya = *(const float4*)&Ys[f * 128 + ty * 8];
        float4 yb4 = *(const float4*)&Ys[f * 128 + ty * 8 + 4];
        float4 xa = *(const float4*)&Xs[f * 128 + tx * 8];
        float4 xb4 = *(const float4*)&Xs[f * 128 + tx * 8 + 4];
        unsigned long long xp0, xp1, xp2, xp3;
        asm("mov.b64 %0,{%1,%2};" : "=l"(xp0) : "f"(xa.x),  "f"(xa.y));
        asm("mov.b64 %0,{%1,%2};" : "=l"(xp1) : "f"(xa.z),  "f"(xa.w));
        asm("mov.b64 %0,{%1,%2};" : "=l"(xp2) : "f"(xb4.x), "f"(xb4.y));
        asm("mov.b64 %0,{%1,%2};" : "=l"(xp3) : "f"(xb4.z), "f"(xb4.w));
        float yv[8] = {ya.x, ya.y, ya.z, ya.w, yb4.x, yb4.y, yb4.z, yb4.w};
#pragma unroll
        for (int i = 0; i < 8; ++i) {
            unsigned long long yd;
            asm("mov.b64 %0,{%1,%1};" : "=l"(yd) : "f"(yv[i]));
            asm("fma.rn.f32x2 %0,%1,%2,%0;" : "+l"(acc2[i][0]) : "l"(yd), "l"(xp0));
            asm("fma.rn.f32x2 %0,%1,%2,%0;" : "+l"(acc2[i][1]) : "l"(yd), "l"(xp1));
            asm("fma.rn.f32x2 %0,%1,%2,%0;" : "+l"(acc2[i][2]) : "l"(yd), "l"(xp2));
            asm("fma.rn.f32x2 %0,%1,%2,%0;" : "+l"(acc2[i][3]) : "l"(yd), "l"(xp3));
        }
    }

    int tbase = t0 + tx * 8;
    float xsqv[8];
#pragma unroll
    for (int j = 0; j < 8; ++j) xsqv[j] = g_xsq[b * TXX + tbase + j];

#pragma unroll
    for (int i = 0; i < 8; ++i) {
        int yg = y0 + ty * 8 + i;
        if (yg >= ylen) continue;
        float ysv = g_ysq[b * TYY + yg];
        float av[8];
#pragma unroll
        for (int j2 = 0; j2 < 4; ++j2) {
            float lo, hi;
            asm("mov.b64 {%0,%1}, %2;" : "=f"(lo), "=f"(hi) : "l"(acc2[i][j2]));
            av[j2 * 2] = lo; av[j2 * 2 + 1] = hi;
        }
        float ov[8];
#pragma unroll
        for (int j = 0; j < 8; ++j) {
            float val = ((ysv + av[j]) + xsqv[j]) + CONSTF;
            ov[j] = (tbase + j < xlen) ? val : NEGF;
        }
        float* vout = g_v + ((size_t)b * TYY + yg) * TXX + tbase;
        *(float4*)(vout + 0) = make_float4(ov[0], ov[1], ov[2], ov[3]);
        *(float4*)(vout + 4) = make_float4(ov[4], ov[5], ov[6], ov[7]);
    }
}

// ---------------------------------------------------------------------------
__device__ __forceinline__ int mbar_try_wait(uint32_t mb, uint32_t par) {
    uint32_t done;
    asm volatile(
        "{\n\t.reg .pred p;\n\t"
        "mbarrier.try_wait.parity.acquire.cta.shared::cta.b64 p, [%1], %2, 0x989680;\n\t"
        "selp.b32 %0,1,0,p;\n\t}"
        : "=r"(done) : "r"(mb), "r"(par) : "memory");
    return (int)done;
}

// ---------------------------------------------------------------------------
// DP forward + backtrack.  TWO warps per batch, column-split wavefront:
// warp0 owns t=0..191, warp1 owns t=192..383 and lags one row.  Carry
// q[191] flows warp0 -> warp1 via a 4-deep smem ring (write step s, read
// step s+2).  One __syncthreads per step.  6 cols/lane, 6-bit decision
// byte per lane per row.  Backtrack prefetches THREE candidate bytes
// {w0, w0-1, w0-2}: idx can drop <=8 per 8-row batch, crossing up to two
// 6-column byte boundaries.
__global__ __launch_bounds__(64) void dp_kernel(const int* __restrict__ xl,
                                                const int* __restrict__ yl) {
    extern __shared__ float smf[];
    float* ring = smf;                                        // [DSLOT][TXX]
    unsigned char* sdec = (unsigned char*)smf + SDEC_OFF;     // [TYY+8][64]
    float* carry_buf = (float*)((char*)smf + CARRY_OFF);      // [4]

    int tid = threadIdx.x;
    int wid = tid >> 5, lane = tid & 31;
    int b = blockIdx.x;
    int ylen = yl[b], xlen = xl[b];

    const float* vb = g_v + (size_t)b * TYY * TXX;
    uint32_t ring_base = (uint32_t)__cvta_generic_to_shared(ring);
    uint32_t mbar_addr = ring_base + MBAR_OFF;

    if (tid == 0) {
#pragma unroll
        for (int m = 0; m < 4; ++m)
            asm volatile("mbarrier.init.shared.b64 [%0], 1;"
                         :: "r"(mbar_addr + m * 8) : "memory");
    }
    if (tid < 4) carry_buf[tid] = NEGF;
    __syncthreads();
    asm volatile("fence.proxy.async.shared::cta;" ::: "memory");

#define DP_ISSUE(bi_)                                                          \
    do {                                                                       \
        if (tid == 0) {                                                        \
            int r0_ = (bi_) * 8;                                               \
            if (r0_ + 8 > TYY) r0_ = TYY - 8;                                  \
            uint32_t mb_ = mbar_addr + ((bi_) & 3) * 8;                        \
            uint32_t dst_ = ring_base + (uint32_t)(((bi_) & 3) * BLK_BYTES);   \
            const float* src_ = vb + (size_t)r0_ * TXX;                        \
            asm volatile("mbarrier.arrive.expect_tx.shared.b64 _, [%0], %1;"   \
                         :: "r"(mb_), "r"((uint32_t)BLK_BYTES) : "memory");    \
            asm volatile(                                                      \
                "cp.async.bulk.shared::cta.global.mbarrier::complete_tx::bytes"\
                " [%0], [%1], %2, [%3];"                                       \
                :: "r"(dst_), "l"(src_), "r"((uint32_t)BLK_BYTES), "r"(mb_)    \
                : "memory");                                                   \
        }                                                                      \
    } while (0)

#define DP_WAIT(bi_)                                                           \
    do {                                                                       \
        uint32_t mb_ = mbar_addr + ((bi_) & 3) * 8;                            \
        uint32_t par_ = (uint32_t)(((bi_) >> 2) & 1);                          \
        while (!mbar_try_wait(mb_, par_)) { }                                  \
    } while (0)

// per-warp row body: 6 columns starting at wid*192 + lane*6
#define DP_ROW(row_, carry_expr_, dec_off_)                                    \
    do {                                                                       \
        const float* rp_ = ring + ((row_) & (DSLOT - 1)) * TXX +               \
                           wid * 192 + lane * 6;                               \
        float2 a0_ = *(const float2*)(rp_ + 0);                                \
        float2 a1_ = *(const float2*)(rp_ + 2);                                \
        float2 a2_ = *(const float2*)(rp_ + 4);                                \
        float carry_ = __shfl_up_sync(0xffffffffu, q[5], 1);                   \
        if (lane == 0) carry_ = (carry_expr_);                                 \
        float vv_[6] = {a0_.x, a0_.y, a1_.x, a1_.y, a2_.x, a2_.y};             \
        unsigned bits_ = 0u;                                                   \
        _Pragma("unroll")                                                      \
        for (int j_ = 5; j_ >= 1; --j_)                                        \
            bits_ |= ((q[j_] < q[j_ - 1]) ? 1u : 0u) << j_;                    \
        bits_ |= (q[0] < carry_) ? 1u : 0u;                                    \
        _Pragma("unroll")                                                      \
        for (int j_ = 5; j_ >= 1; --j_)                                        \
            q[j_] = vv_[j_] + fmaxf(q[j_], q[j_ - 1]);                         \
        q[0] = vv_[0] + fmaxf(q[0], carry_);                                   \
        sdec[(row_) * 64 + (dec_off_) + lane] = (unsigned char)bits_;          \
    } while (0)

    DP_ISSUE(0);
    DP_ISSUE(1);

    float q[6];
#pragma unroll
    for (int j = 0; j < 6; ++j) q[j] = NEGF;
    if (tid == 0) q[0] = 0.0f;

    int nblk = (ylen + 7) >> 3;
    for (int bi = 0; bi < nblk; ++bi) {
        DP_ISSUE(bi + 2);
        DP_WAIT(bi);
        int yb = bi * 8;
#pragma unroll
        for (int k = 0; k < 8; ++k) {
            int step = yb + k;
            if (wid == 0) {
                if (step < ylen) {
                    DP_ROW(step, NEGF, 0);
                    if (lane == 31) carry_buf[step & 3] = q[5];
                }
            } else {
                int row = step - 1;
                if (row >= 0 && row < ylen) {
                    DP_ROW(row, carry_buf[(step - 2) & 3], 32);
                }
            }
            __syncthreads();
        }
    }
    // tail: when ylen%8==0 warp1 hasn't processed row ylen-1
    if ((ylen & 7) == 0) {
        if (wid == 1) {
            int step = nblk * 8;
            int row = ylen - 1;
            DP_ROW(row, carry_buf[(step - 2) & 3], 32);
        }
        __syncthreads();
    }
    // drain outstanding blocks
    DP_WAIT(nblk);
    DP_WAIT(nblk + 1);
    __syncthreads();

#pragma unroll
    for (int j = 0; j < 6; ++j) g_dur[b * TXX + tid * 6 + j] = 0.0f;
    __syncthreads();

    // --------- backtrack: thread-0 scalar, 8-row batched byte loads --------
    if (tid == 0) {
        int idx = xlen - 1;
        int w = idx / 6, r = idx - w * 6;
        int cnt = 0;
        int* gi = g_idx + b * TYY;
        int yy = ylen - 1;
        while (yy >= 0) {
            int w0 = w;
            int w1 = (w0 > 0) ? w0 - 1 : 0;
            int w2 = (w0 > 1) ? w0 - 2 : 0;
            unsigned wa[8], wb2[8], wc[8];
            if (yy >= 7) {
#pragma unroll
                for (int k = 0; k < 8; ++k)
                    wa[k] = (unsigned)sdec[(yy - k) * 64 + w0];
#pragma unroll
                for (int k = 0; k < 8; ++k)
                    wb2[k] = (unsigned)sdec[(yy - k) * 64 + w1];
#pragma unroll
                for (int k = 0; k < 8; ++k)
                    wc[k] = (unsigned)sdec[(yy - k) * 64 + w2];
#pragma unroll
                for (int k = 0; k < 8; ++k) {
                    int row = yy - k;
                    unsigned use = (w == w0) ? wa[k]
                                 : ((w == w0 - 1) ? wb2[k] : wc[k]);
                    gi[row] = idx;
                    cnt++;
                    bool move = (idx != 0) && (row > 0) &&
                                ((idx == row) || (((use >> r) & 1u) != 0u));
                    if (move) {
                        g_dur[b * TXX + idx] = (float)cnt;
                        cnt = 0; idx--;
                        if (--r < 0) { r = 5; w--; }
                    }
                }
                yy -= 8;
            } else {
                int row = yy;
                unsigned use = (unsigned)sdec[row * 64 + w];
                gi[row] = idx;
                cnt++;
                bool move = (idx != 0) && (row > 0) &&
                            ((idx == row) || (((use >> r) & 1u) != 0u));
                if (move) {
                    g_dur[b * TXX + idx] = (float)cnt;
                    cnt = 0; idx--;
                    if (--r < 0) { r = 5; w--; }
                }
                yy -= 1;
            }
        }
        g_dur[b * TXX + idx] = (float)cnt;
    }
}

// ---------------------------------------------------------------------------
// attn[b][t][s] = (s < ylen && g_idx[b][s] == t) ? 1 : 0
__global__ __launch_bounds__(128) void attn_kernel(const int* __restrict__ yl,
                                                   float* __restrict__ out) {
    int b = blockIdx.y;
    int t = blockIdx.x;
    int tid = threadIdx.x;
    int ylen = yl[b];
    const int* gi = g_idx + b * TYY;
    float* o = out + ((size_t)b * TXX + t) * TYY;
#pragma unroll
    for (int it = 0; it < 3; ++it) {
        int s4 = tid + it * 128;
        int s = s4 * 4;
        int4 iv = *(const int4*)(gi + s);
        float4 ov;
        ov.x = (s + 0 < ylen && iv.x == t) ? 1.f : 0.f;
        ov.y = (s + 1 < ylen && iv.y == t) ? 1.f : 0.f;
        ov.z = (s + 2 < ylen && iv.z == t) ? 1.f : 0.f;
        ov.w = (s + 3 < ylen && iv.w == t) ? 1.f : 0.f;
        *(float4*)(o + s) = ov;
    }
}

// ---------------------------------------------------------------------------
// loss + durations tail
__global__ __launch_bounds__(256) void loss_kernel(const float* __restrict__ pred,
                                                   const int* __restrict__ xl,
                                                   float* __restrict__ out,
                                                   int write_tail) {
    __shared__ float red[256];
    int tid = threadIdx.x;
    float s = 0.f;
    for (int i = tid; i < BB * TXX; i += 256) {
        int b = i / TXX, t = i - b * TXX;
        float dur = g_dur[i];
        float tl = (t < xl[b]) ? logf(dur + 1e-8f) : 0.0f;
        float d = pred[i] - tl;
        s += d * d;
        if (write_tail) out[ATTN_SZ + 1 + i] = dur;
    }
    red[tid] = s;
    __syncthreads();
    for (int off = 128; off > 0; off >>= 1) {
        if (tid < off) red[tid] += red[tid + off];
        __syncthreads();
    }
    if (tid == 0 && write_tail) {
        int sx = 0;
        for (int bb2 = 0; bb2 < BB; ++bb2) sx += xl[bb2];
        out[ATTN_SZ] = red[0] / (float)sx;
    }
}

// ---------------------------------------------------------------------------
extern "C" void kernel_launch(void* const* d_in, const int* in_sizes, int n_in,
                              void* d_out, int out_size) {
    const float* x    = (const float*)d_in[0];
    const float* y    = (const float*)d_in[1];
    const int*   xlen = (const int*)d_in[4];
    const int*   ylen = (const int*)d_in[5];
    const float* pred = (const float*)d_in[6];
    const float* W    = (const float*)d_in[7];
    const float* bias = (const float*)d_in[8];
    float* out = (float*)d_out;

    cudaFuncSetAttribute(cross_kernel, cudaFuncAttributeMaxDynamicSharedMemorySize,
                         2 * 80 * 128 * (int)sizeof(float));
    cudaFuncSetAttribute(dp_kernel, cudaFuncAttributeMaxDynamicSharedMemorySize,
                         DP_SMEM);

    ysq_kernel<<<dim3(TYY / 256, BB), 256>>>(y);
    xp_kernel<<<dim3(TXX / 128, BB), 160>>>(x, W, bias);
    cross_kernel<<<dim3(TXX / 128, TYY / 128, BB), 256,
                   2 * 80 * 128 * sizeof(float)>>>(y, xlen, ylen);
    dp_kernel<<<BB, 64, DP_SMEM>>>(xlen, ylen);
    attn_kernel<<<dim3(TXX, BB), 128>>>(ylen, out);

    int write_tail = ((size_t)out_size >= ATTN_SZ + 1 + BB * TXX) ? 1 : 0;
    loss_kernel<<<1, 256>>>(pred, xlen, out, write_tail);
}

// round 13
// speedup vs baseline: 1.0917x; 1.0917x over previous
#include <cuda_runtime.h>
#include <stdint.h>
#include <math.h>

#define BB 32
#define TXX 384
#define TYY 1536
#define DIMK 256
#define NF 80
#define NEGF (-1000000000.0f)
#define CONSTF (-73.51508265637381f)   /* -0.5*log(2*pi)*80 */

#define ATTN_SZ ((size_t)BB * TXX * TYY)

// DP ring: 32 rows = 4 blocks of 8 rows
#define DSLOT 32
#define BLK_BYTES (8 * TXX * 4)   /* 12288 */
#define RING_BYTES (DSLOT * TXX * 4)              /* 49152 */
#define SDEC_OFF  RING_BYTES                      /* uint8[TYY+8][64] */
#define CARRY_OFF (SDEC_OFF + (TYY + 8) * 64)     /* float[32] */
#define MBAR_OFF  (CARRY_OFF + 128)
#define DP_SMEM   (MBAR_OFF + 48)

// ---------------- scratch (static device memory; no allocation) -------------
__device__ float g_xp[(size_t)BB * NF * TXX];          // [b][f][t]
__device__ float g_xsq[BB * TXX];
__device__ float g_ysq[BB * TYY];
__device__ float g_v[(size_t)BB * TYY * TXX];          // [b][y][t]
__device__ int   g_idx[BB * TYY];
__device__ float g_dur[BB * TXX];

// ---------------------------------------------------------------------------
// y_square[b][s] = -0.5 * sum_f y[b][f][s]^2
__global__ void ysq_kernel(const float* __restrict__ y) {
    int b = blockIdx.y;
    int s = blockIdx.x * 256 + threadIdx.x;
    if (s >= TYY) return;
    const float* yb = y + (size_t)b * NF * TYY + s;
    float sum = 0.f;
#pragma unroll
    for (int f = 0; f < NF; ++f) {
        float v = yb[(size_t)f * TYY];
        sum += v * v;
    }
    g_ysq[b * TYY + s] = -0.5f * sum;
}

// ---------------------------------------------------------------------------
// xp[b][f][t] = sum_d x[b][t][d] * W[f][d] + bias[f];  xsq[b][t] = -0.5*sum_f xp^2
__global__ __launch_bounds__(160) void xp_kernel(const float* __restrict__ x,
                                                 const float* __restrict__ W,
                                                 const float* __restrict__ bias) {
    __shared__ float xs[32][128];   // [k][t]
    __shared__ float ws[32][80];    // [k][f]
    __shared__ float part[10][128];

    int b  = blockIdx.y;
    int t0 = blockIdx.x * 128;
    int tid = threadIdx.x;
    int tx = tid & 15;        // t-group
    int fg = tid >> 4;        // f-group (0..9)

    float acc[8][8];
#pragma unroll
    for (int i = 0; i < 8; ++i)
#pragma unroll
        for (int j = 0; j < 8; ++j) acc[i][j] = 0.f;

    const float* xb = x + ((size_t)b * TXX + t0) * DIMK;

    for (int k0 = 0; k0 < DIMK; k0 += 32) {
        for (int i = tid; i < 1024; i += 160) {     // 128 t x 8 float4
            int t = i >> 3, kq = i & 7;
            float4 v = *(const float4*)(xb + (size_t)t * DIMK + k0 + kq * 4);
            xs[kq * 4 + 0][t] = v.x; xs[kq * 4 + 1][t] = v.y;
            xs[kq * 4 + 2][t] = v.z; xs[kq * 4 + 3][t] = v.w;
        }
        for (int i = tid; i < 640; i += 160) {      // 80 f x 8 float4
            int f = i >> 3, kq = i & 7;
            float4 v = *(const float4*)(W + (size_t)f * DIMK + k0 + kq * 4);
            ws[kq * 4 + 0][f] = v.x; ws[kq * 4 + 1][f] = v.y;
            ws[kq * 4 + 2][f] = v.z; ws[kq * 4 + 3][f] = v.w;
        }
        __syncthreads();
#pragma unroll 8
        for (int kk = 0; kk < 32; ++kk) {
            float4 xa = *(const float4*)&xs[kk][tx * 8];
            float4 xb4 = *(const float4*)&xs[kk][tx * 8 + 4];
            float4 wa = *(const float4*)&ws[kk][fg * 8];
            float4 wb4 = *(const float4*)&ws[kk][fg * 8 + 4];
            float xv[8] = {xa.x, xa.y, xa.z, xa.w, xb4.x, xb4.y, xb4.z, xb4.w};
            float wv[8] = {wa.x, wa.y, wa.z, wa.w, wb4.x, wb4.y, wb4.z, wb4.w};
#pragma unroll
            for (int i = 0; i < 8; ++i)
#pragma unroll
                for (int j = 0; j < 8; ++j) acc[i][j] += xv[i] * wv[j];
        }
        __syncthreads();
    }

    float bv[8];
#pragma unroll
    for (int j = 0; j < 8; ++j) bv[j] = bias[fg * 8 + j];

    float ss[8];
#pragma unroll
    for (int i = 0; i < 8; ++i) ss[i] = 0.f;

#pragma unroll
    for (int i = 0; i < 8; ++i) {
        int t = t0 + tx * 8 + i;
#pragma unroll
        for (int j = 0; j < 8; ++j) {
            float v = acc[i][j] + bv[j];
            g_xp[((size_t)b * NF + fg * 8 + j) * TXX + t] = v;
            ss[i] += v * v;
        }
    }
#pragma unroll
    for (int i = 0; i < 8; ++i) part[fg][tx * 8 + i] = ss[i];
    __syncthreads();
    if (tid < 128) {
        float s = 0.f;
#pragma unroll
        for (int g = 0; g < 10; ++g) s += part[g][tid];
        g_xsq[b * TXX + t0 + tid] = -0.5f * s;
    }
}

// ---------------------------------------------------------------------------
// v[b][y][t] = ysq[y] + sum_f xp[b][f][t]*y[b][f][y] + xsq[t] + CONST  (masked)
// Packed f32x2 FMA inner loop.  Tiles with t0 >= xlen or t0 > y0+128 skipped.
__global__ __launch_bounds__(256) void cross_kernel(const float* __restrict__ y,
                                                    const int* __restrict__ xl,
                                                    const int* __restrict__ yl) {
    extern __shared__ float sm[];
    float* Ys = sm;            // [80][128]
    float* Xs = sm + 80 * 128; // [80][128]

    int b  = blockIdx.z;
    int y0 = blockIdx.y * 128;
    int t0 = blockIdx.x * 128;
    int ylen = yl[b], xlen = xl[b];
    if (y0 >= ylen) return;
    if (t0 >= xlen) return;
    if (t0 > y0 + 128) return;

    int tid = threadIdx.x;

    const float* yb = y + (size_t)b * NF * TYY;
    for (int i = tid; i < 2560; i += 256) {
        int f = i >> 5, q = i & 31;
        *(float4*)&Ys[f * 128 + q * 4] =
            *(const float4*)(yb + (size_t)f * TYY + y0 + q * 4);
    }
    const float* xpb = g_xp + (size_t)b * NF * TXX;
    for (int i = tid; i < 2560; i += 256) {
        int f = i >> 5, q = i & 31;
        *(float4*)&Xs[f * 128 + q * 4] =
            *(const float4*)(xpb + (size_t)f * TXX + t0 + q * 4);
    }
    __syncthreads();

    int tx = tid & 15;   // t
    int ty = tid >> 4;   // y

    unsigned long long acc2[8][4];
#pragma unroll
    for (int i = 0; i < 8; ++i)
#pragma unroll
        for (int j = 0; j < 4; ++j) acc2[i][j] = 0ull;

#pragma unroll 4
    for (int f = 0; f < NF; ++f) {
        float4 ya = *(const float4*)&Ys[f * 128 + ty * 8];
        float4 yb4 = *(const float4*)&Ys[f * 128 + ty * 8 + 4];
        float4 xa = *(const float4*)&Xs[f * 128 + tx * 8];
        float4 xb4 = *(const float4*)&Xs[f * 128 + tx * 8 + 4];
        unsigned long long xp0, xp1, xp2, xp3;
        asm("mov.b64 %0,{%1,%2};" : "=l"(xp0) : "f"(xa.x),  "f"(xa.y));
        asm("mov.b64 %0,{%1,%2};" : "=l"(xp1) : "f"(xa.z),  "f"(xa.w));
        asm("mov.b64 %0,{%1,%2};" : "=l"(xp2) : "f"(xb4.x), "f"(xb4.y));
        asm("mov.b64 %0,{%1,%2};" : "=l"(xp3) : "f"(xb4.z), "f"(xb4.w));
        float yv[8] = {ya.x, ya.y, ya.z, ya.w, yb4.x, yb4.y, yb4.z, yb4.w};
#pragma unroll
        for (int i = 0; i < 8; ++i) {
            unsigned long long yd;
            asm("mov.b64 %0,{%1,%1};" : "=l"(yd) : "f"(yv[i]));
            asm("fma.rn.f32x2 %0,%1,%2,%0;" : "+l"(acc2[i][0]) : "l"(yd), "l"(xp0));
            asm("fma.rn.f32x2 %0,%1,%2,%0;" : "+l"(acc2[i][1]) : "l"(yd), "l"(xp1));
            asm("fma.rn.f32x2 %0,%1,%2,%0;" : "+l"(acc2[i][2]) : "l"(yd), "l"(xp2));
            asm("fma.rn.f32x2 %0,%1,%2,%0;" : "+l"(acc2[i][3]) : "l"(yd), "l"(xp3));
        }
    }

    int tbase = t0 + tx * 8;
    float xsqv[8];
#pragma unroll
    for (int j = 0; j < 8; ++j) xsqv[j] = g_xsq[b * TXX + tbase + j];

#pragma unroll
    for (int i = 0; i < 8; ++i) {
        int yg = y0 + ty * 8 + i;
        if (yg >= ylen) continue;
        float ysv = g_ysq[b * TYY + yg];
        float av[8];
#pragma unroll
        for (int j2 = 0; j2 < 4; ++j2) {
            float lo, hi;
            asm("mov.b64 {%0,%1}, %2;" : "=f"(lo), "=f"(hi) : "l"(acc2[i][j2]));
            av[j2 * 2] = lo; av[j2 * 2 + 1] = hi;
        }
        float ov[8];
#pragma unroll
        for (int j = 0; j < 8; ++j) {
            float val = ((ysv + av[j]) + xsqv[j]) + CONSTF;
            ov[j] = (tbase + j < xlen) ? val : NEGF;
        }
        float* vout = g_v + ((size_t)b * TYY + yg) * TXX + tbase;
        *(float4*)(vout + 0) = make_float4(ov[0], ov[1], ov[2], ov[3]);
        *(float4*)(vout + 4) = make_float4(ov[4], ov[5], ov[6], ov[7]);
    }
}

// ---------------------------------------------------------------------------
__device__ __forceinline__ int mbar_try_wait(uint32_t mb, uint32_t par) {
    uint32_t done;
    asm volatile(
        "{\n\t.reg .pred p;\n\t"
        "mbarrier.try_wait.parity.acquire.cta.shared::cta.b64 p, [%1], %2, 0x989680;\n\t"
        "selp.b32 %0,1,0,p;\n\t}"
        : "=r"(done) : "r"(mb), "r"(par) : "memory");
    return (int)done;
}

// ---------------------------------------------------------------------------
// DP forward + backtrack.  TWO warps per batch, BLOCK-staggered wavefront:
// warp0 processes 8-row block bi while warp1 processes block bi-1.  ONE
// __syncthreads per 8-row block (R12 synced per row -> 28% issue).  Carry
// q[191] after warp0's row r is written to carry_buf[r&31]; warp1's row r
// reads carry_buf[(r-1)&31] (written >= 1 block earlier; slots disjoint
// mod 32).  6 cols/lane, 6-bit decision byte per row; backtrack with
// 3-byte prefetch (machinery validated by R12's passing rel_err).
__global__ __launch_bounds__(64) void dp_kernel(const int* __restrict__ xl,
                                                const int* __restrict__ yl) {
    extern __shared__ float smf[];
    float* ring = smf;                                        // [DSLOT][TXX]
    unsigned char* sdec = (unsigned char*)smf + SDEC_OFF;     // [TYY+8][64]
    float* carry_buf = (float*)((char*)smf + CARRY_OFF);      // [32]

    int tid = threadIdx.x;
    int wid = tid >> 5, lane = tid & 31;
    int b = blockIdx.x;
    int ylen = yl[b], xlen = xl[b];

    const float* vb = g_v + (size_t)b * TYY * TXX;
    uint32_t ring_base = (uint32_t)__cvta_generic_to_shared(ring);
    uint32_t mbar_addr = ring_base + MBAR_OFF;

    if (tid == 0) {
#pragma unroll
        for (int m = 0; m < 4; ++m)
            asm volatile("mbarrier.init.shared.b64 [%0], 1;"
                         :: "r"(mbar_addr + m * 8) : "memory");
    }
    if (tid < 32) carry_buf[tid] = NEGF;
    __syncthreads();
    asm volatile("fence.proxy.async.shared::cta;" ::: "memory");

#define DP_ISSUE(bi_)                                                          \
    do {                                                                       \
        if (tid == 0) {                                                        \
            int r0_ = (bi_) * 8;                                               \
            if (r0_ + 8 > TYY) r0_ = TYY - 8;                                  \
            uint32_t mb_ = mbar_addr + ((bi_) & 3) * 8;                        \
            uint32_t dst_ = ring_base + (uint32_t)(((bi_) & 3) * BLK_BYTES);   \
            const float* src_ = vb + (size_t)r0_ * TXX;                        \
            asm volatile("mbarrier.arrive.expect_tx.shared.b64 _, [%0], %1;"   \
                         :: "r"(mb_), "r"((uint32_t)BLK_BYTES) : "memory");    \
            asm volatile(                                                      \
                "cp.async.bulk.shared::cta.global.mbarrier::complete_tx::bytes"\
                " [%0], [%1], %2, [%3];"                                       \
                :: "r"(dst_), "l"(src_), "r"((uint32_t)BLK_BYTES), "r"(mb_)    \
                : "memory");                                                   \
        }                                                                      \
    } while (0)

#define DP_WAIT(bi_)                                                           \
    do {                                                                       \
        uint32_t mb_ = mbar_addr + ((bi_) & 3) * 8;                            \
        uint32_t par_ = (uint32_t)(((bi_) >> 2) & 1);                          \
        while (!mbar_try_wait(mb_, par_)) { }                                  \
    } while (0)

// per-warp row body: 6 columns starting at wid*192 + lane*6
#define DP_ROW(row_, carry_expr_, dec_off_)                                    \
    do {                                                                       \
        const float* rp_ = ring + ((row_) & (DSLOT - 1)) * TXX +               \
                           wid * 192 + lane * 6;                               \
        float2 a0_ = *(const float2*)(rp_ + 0);                                \
        float2 a1_ = *(const float2*)(rp_ + 2);                                \
        float2 a2_ = *(const float2*)(rp_ + 4);                                \
        float carry_ = __shfl_up_sync(0xffffffffu, q[5], 1);                   \
        if (lane == 0) carry_ = (carry_expr_);                                 \
        float vv_[6] = {a0_.x, a0_.y, a1_.x, a1_.y, a2_.x, a2_.y};             \
        unsigned bits_ = 0u;                                                   \
        _Pragma("unroll")                                                      \
        for (int j_ = 5; j_ >= 1; --j_)                                        \
            bits_ |= ((q[j_] < q[j_ - 1]) ? 1u : 0u) << j_;                    \
        bits_ |= (q[0] < carry_) ? 1u : 0u;                                    \
        _Pragma("unroll")                                                      \
        for (int j_ = 5; j_ >= 1; --j_)                                        \
            q[j_] = vv_[j_] + fmaxf(q[j_], q[j_ - 1]);                         \
        q[0] = vv_[0] + fmaxf(q[0], carry_);                                   \
        sdec[(row_) * 64 + (dec_off_) + lane] = (unsigned char)bits_;          \
    } while (0)

    DP_ISSUE(0);
    DP_ISSUE(1);

    float q[6];
#pragma unroll
    for (int j = 0; j < 6; ++j) q[j] = NEGF;
    if (tid == 0) q[0] = 0.0f;

    int nblk = (ylen + 7) >> 3;
    for (int bi = 0; bi <= nblk; ++bi) {
        if (bi + 2 < nblk) DP_ISSUE(bi + 2);
        if (bi < nblk) DP_WAIT(bi);
        if (wid == 0) {
            if (bi < nblk) {
                int r0 = bi * 8;
                int r1 = r0 + 8; if (r1 > ylen) r1 = ylen;
                for (int r = r0; r < r1; ++r) {
                    DP_ROW(r, NEGF, 0);
                    if (lane == 31) carry_buf[r & 31] = q[5];
                }
            }
        } else {
            int r0 = bi * 8 - 8; if (r0 < 0) r0 = 0;
            int r1 = bi * 8; if (r1 > ylen) r1 = ylen;
            for (int r = r0; r < r1; ++r) {
                DP_ROW(r, carry_buf[(r - 1) & 31], 32);
            }
        }
        __syncthreads();
    }

#pragma unroll
    for (int j = 0; j < 6; ++j) g_dur[b * TXX + tid * 6 + j] = 0.0f;
    __syncthreads();

    // --------- backtrack: thread-0 scalar, 8-row batched byte loads --------
    if (tid == 0) {
        int idx = xlen - 1;
        int w = idx / 6, r = idx - w * 6;
        int cnt = 0;
        int* gi = g_idx + b * TYY;
        int yy = ylen - 1;
        while (yy >= 0) {
            int w0 = w;
            int w1 = (w0 > 0) ? w0 - 1 : 0;
            int w2 = (w0 > 1) ? w0 - 2 : 0;
            unsigned wa[8], wb2[8], wc[8];
            if (yy >= 7) {
#pragma unroll
                for (int k = 0; k < 8; ++k)
                    wa[k] = (unsigned)sdec[(yy - k) * 64 + w0];
#pragma unroll
                for (int k = 0; k < 8; ++k)
                    wb2[k] = (unsigned)sdec[(yy - k) * 64 + w1];
#pragma unroll
                for (int k = 0; k < 8; ++k)
                    wc[k] = (unsigned)sdec[(yy - k) * 64 + w2];
#pragma unroll
                for (int k = 0; k < 8; ++k) {
                    int row = yy - k;
                    unsigned use = (w == w0) ? wa[k]
                                 : ((w == w0 - 1) ? wb2[k] : wc[k]);
                    gi[row] = idx;
                    cnt++;
                    bool move = (idx != 0) && (row > 0) &&
                                ((idx == row) || (((use >> r) & 1u) != 0u));
                    if (move) {
                        g_dur[b * TXX + idx] = (float)cnt;
                        cnt = 0; idx--;
                        if (--r < 0) { r = 5; w--; }
                    }
                }
                yy -= 8;
            } else {
                int row = yy;
                unsigned use = (unsigned)sdec[row * 64 + w];
                gi[row] = idx;
                cnt++;
                bool move = (idx != 0) && (row > 0) &&
                            ((idx == row) || (((use >> r) & 1u) != 0u));
                if (move) {
                    g_dur[b * TXX + idx] = (float)cnt;
                    cnt = 0; idx--;
                    if (--r < 0) { r = 5; w--; }
                }
                yy -= 1;
            }
        }
        g_dur[b * TXX + idx] = (float)cnt;
    }
}

// ---------------------------------------------------------------------------
// attn[b][t][s] = (s < ylen && g_idx[b][s] == t) ? 1 : 0
__global__ __launch_bounds__(128) void attn_kernel(const int* __restrict__ yl,
                                                   float* __restrict__ out) {
    int b = blockIdx.y;
    int t = blockIdx.x;
    int tid = threadIdx.x;
    int ylen = yl[b];
    const int* gi = g_idx + b * TYY;
    float* o = out + ((size_t)b * TXX + t) * TYY;
#pragma unroll
    for (int it = 0; it < 3; ++it) {
        int s4 = tid + it * 128;
        int s = s4 * 4;
        int4 iv = *(const int4*)(gi + s);
        float4 ov;
        ov.x = (s + 0 < ylen && iv.x == t) ? 1.f : 0.f;
        ov.y = (s + 1 < ylen && iv.y == t) ? 1.f : 0.f;
        ov.z = (s + 2 < ylen && iv.z == t) ? 1.f : 0.f;
        ov.w = (s + 3 < ylen && iv.w == t) ? 1.f : 0.f;
        *(float4*)(o + s) = ov;
    }
}

// ---------------------------------------------------------------------------
// loss + durations tail
__global__ __launch_bounds__(256) void loss_kernel(const float* __restrict__ pred,
                                                   const int* __restrict__ xl,
                                                   float* __restrict__ out,
                                                   int write_tail) {
    __shared__ float red[256];
    int tid = threadIdx.x;
    float s = 0.f;
    for (int i = tid; i < BB * TXX; i += 256) {
        int b = i / TXX, t = i - b * TXX;
        float dur = g_dur[i];
        float tl = (t < xl[b]) ? logf(dur + 1e-8f) : 0.0f;
        float d = pred[i] - tl;
        s += d * d;
        if (write_tail) out[ATTN_SZ + 1 + i] = dur;
    }
    red[tid] = s;
    __syncthreads();
    for (int off = 128; off > 0; off >>= 1) {
        if (tid < off) red[tid] += red[tid + off];
        __syncthreads();
    }
    if (tid == 0 && write_tail) {
        int sx = 0;
        for (int bb2 = 0; bb2 < BB; ++bb2) sx += xl[bb2];
        out[ATTN_SZ] = red[0] / (float)sx;
    }
}

// ---------------------------------------------------------------------------
extern "C" void kernel_launch(void* const* d_in, const int* in_sizes, int n_in,
                              void* d_out, int out_size) {
    const float* x    = (const float*)d_in[0];
    const float* y    = (const float*)d_in[1];
    const int*   xlen = (const int*)d_in[4];
    const int*   ylen = (const int*)d_in[5];
    const float* pred = (const float*)d_in[6];
    const float* W    = (const float*)d_in[7];
    const float* bias = (const float*)d_in[8];
    float* out = (float*)d_out;

    cudaFuncSetAttribute(cross_kernel, cudaFuncAttributeMaxDynamicSharedMemorySize,
                         2 * 80 * 128 * (int)sizeof(float));
    cudaFuncSetAttribute(dp_kernel, cudaFuncAttributeMaxDynamicSharedMemorySize,
                         DP_SMEM);

    ysq_kernel<<<dim3(TYY / 256, BB), 256>>>(y);
    xp_kernel<<<dim3(TXX / 128, BB), 160>>>(x, W, bias);
    cross_kernel<<<dim3(TXX / 128, TYY / 128, BB), 256,
                   2 * 80 * 128 * sizeof(float)>>>(y, xlen, ylen);
    dp_kernel<<<BB, 64, DP_SMEM>>>(xlen, ylen);
    attn_kernel<<<dim3(TXX, BB), 128>>>(ylen, out);

    int write_tail = ((size_t)out_size >= ATTN_SZ + 1 + BB * TXX) ? 1 : 0;
    loss_kernel<<<1, 256>>>(pred, xlen, out, write_tail);
}

// round 14
// speedup vs baseline: 1.2586x; 1.1529x over previous
#include <cuda_runtime.h>
#include <stdint.h>
#include <math.h>

#define BB 32
#define TXX 384
#define TYY 1536
#define DIMK 256
#define NF 80
#define NEGF (-1000000000.0f)
#define CONSTF (-73.51508265637381f)   /* -0.5*log(2*pi)*80 */

#define ATTN_SZ ((size_t)BB * TXX * TYY)

// DP ring: 32 rows = 4 blocks of 8 rows (R8 single-warp design)
#define DSLOT 32
#define BLK_BYTES (8 * TXX * 4)   /* 12288 */
#define MBAR_OFF (DSLOT * TXX * 4 + (TYY + 8) * 32 * 2)   /* 147968 */
#define DP_SMEM  (MBAR_OFF + 48)

#define NYT 12                    /* y bands of 128 */
#define NCROSS (NYT * BB * 3)     /* 1152 cross tiles */

// ---------------- scratch (static device memory; no allocation) -------------
__device__ float g_xp[(size_t)BB * NF * TXX];          // [b][f][t]
__device__ float g_xsq[BB * TXX];
__device__ float g_ysq[BB * TYY];
__device__ float g_v[(size_t)BB * TYY * TXX];          // [b][y][t]
__device__ int   g_idx[BB * TYY];
__device__ float g_dur[BB * TXX];
__device__ int   g_cnt[BB * NYT];                      // cross progress counters

// ---------------------------------------------------------------------------
// y_square + zero progress counters (runs before fused kernel every call)
__global__ void ysq_kernel(const float* __restrict__ y) {
    int b = blockIdx.y;
    int s = blockIdx.x * 256 + threadIdx.x;
    if (blockIdx.x == 0 && blockIdx.y == 0) {
        for (int i = threadIdx.x; i < BB * NYT; i += 256) g_cnt[i] = 0;
    }
    if (s >= TYY) return;
    const float* yb = y + (size_t)b * NF * TYY + s;
    float sum = 0.f;
#pragma unroll
    for (int f = 0; f < NF; ++f) {
        float v = yb[(size_t)f * TYY];
        sum += v * v;
    }
    g_ysq[b * TYY + s] = -0.5f * sum;
}

// ---------------------------------------------------------------------------
// xp[b][f][t] = sum_d x[b][t][d] * W[f][d] + bias[f];  xsq[b][t] = -0.5*sum_f xp^2
__global__ __launch_bounds__(160) void xp_kernel(const float* __restrict__ x,
                                                 const float* __restrict__ W,
                                                 const float* __restrict__ bias) {
    __shared__ float xs[32][128];
    __shared__ float ws[32][80];
    __shared__ float part[10][128];

    int b  = blockIdx.y;
    int t0 = blockIdx.x * 128;
    int tid = threadIdx.x;
    int tx = tid & 15;
    int fg = tid >> 4;

    float acc[8][8];
#pragma unroll
    for (int i = 0; i < 8; ++i)
#pragma unroll
        for (int j = 0; j < 8; ++j) acc[i][j] = 0.f;

    const float* xb = x + ((size_t)b * TXX + t0) * DIMK;

    for (int k0 = 0; k0 < DIMK; k0 += 32) {
        for (int i = tid; i < 1024; i += 160) {
            int t = i >> 3, kq = i & 7;
            float4 v = *(const float4*)(xb + (size_t)t * DIMK + k0 + kq * 4);
            xs[kq * 4 + 0][t] = v.x; xs[kq * 4 + 1][t] = v.y;
            xs[kq * 4 + 2][t] = v.z; xs[kq * 4 + 3][t] = v.w;
        }
        for (int i = tid; i < 640; i += 160) {
            int f = i >> 3, kq = i & 7;
            float4 v = *(const float4*)(W + (size_t)f * DIMK + k0 + kq * 4);
            ws[kq * 4 + 0][f] = v.x; ws[kq * 4 + 1][f] = v.y;
            ws[kq * 4 + 2][f] = v.z; ws[kq * 4 + 3][f] = v.w;
        }
        __syncthreads();
#pragma unroll 8
        for (int kk = 0; kk < 32; ++kk) {
            float4 xa = *(const float4*)&xs[kk][tx * 8];
            float4 xb4 = *(const float4*)&xs[kk][tx * 8 + 4];
            float4 wa = *(const float4*)&ws[kk][fg * 8];
            float4 wb4 = *(const float4*)&ws[kk][fg * 8 + 4];
            float xv[8] = {xa.x, xa.y, xa.z, xa.w, xb4.x, xb4.y, xb4.z, xb4.w};
            float wv[8] = {wa.x, wa.y, wa.z, wa.w, wb4.x, wb4.y, wb4.z, wb4.w};
#pragma unroll
            for (int i = 0; i < 8; ++i)
#pragma unroll
                for (int j = 0; j < 8; ++j) acc[i][j] += xv[i] * wv[j];
        }
        __syncthreads();
    }

    float bv[8];
#pragma unroll
    for (int j = 0; j < 8; ++j) bv[j] = bias[fg * 8 + j];

    float ss[8];
#pragma unroll
    for (int i = 0; i < 8; ++i) ss[i] = 0.f;

#pragma unroll
    for (int i = 0; i < 8; ++i) {
        int t = t0 + tx * 8 + i;
#pragma unroll
        for (int j = 0; j < 8; ++j) {
            float v = acc[i][j] + bv[j];
            g_xp[((size_t)b * NF + fg * 8 + j) * TXX + t] = v;
            ss[i] += v * v;
        }
    }
#pragma unroll
    for (int i = 0; i < 8; ++i) part[fg][tx * 8 + i] = ss[i];
    __syncthreads();
    if (tid < 128) {
        float s = 0.f;
#pragma unroll
        for (int g = 0; g < 10; ++g) s += part[g][tid];
        g_xsq[b * TXX + t0 + tid] = -0.5f * s;
    }
}

// ---------------------------------------------------------------------------
__device__ __forceinline__ int mbar_try_wait(uint32_t mb, uint32_t par) {
    uint32_t done;
    asm volatile(
        "{\n\t.reg .pred p;\n\t"
        "mbarrier.try_wait.parity.acquire.cta.shared::cta.b64 p, [%1], %2, 0x989680;\n\t"
        "selp.b32 %0,1,0,p;\n\t}"
        : "=r"(done) : "r"(mb), "r"(par) : "memory");
    return (int)done;
}

// ---------------------------------------------------------------------------
// FUSED kernel: blocks [0,BB) = dp consumers (1 warp, R8 design + band gating);
// blocks [BB, BB+NCROSS) = cross producer tiles ordered band-major so early
// bands complete first.  Producers bump g_cnt[b][band] after threadfence;
// consumers spin on the counter before issuing the TMA fetch of a block.
__global__ __launch_bounds__(256) void fused_kernel(const float* __restrict__ y,
                                                    const int* __restrict__ xl,
                                                    const int* __restrict__ yl) {
    extern __shared__ float sm[];

    if (blockIdx.x >= BB) {
        // ================= cross tile =================
        int idx = blockIdx.x - BB;
        int yi  = idx / (BB * 3);
        int rem = idx - yi * (BB * 3);
        int b   = rem / 3;
        int t0  = (rem - b * 3) * 128;
        int y0  = yi * 128;
        int ylen = yl[b], xlen = xl[b];
        if (y0 >= ylen) return;
        if (t0 >= xlen) return;
        if (t0 > y0 + 128) return;

        float* Ys = sm;            // [80][128]
        float* Xs = sm + 80 * 128; // [80][128]
        int tid = threadIdx.x;

        const float* yb = y + (size_t)b * NF * TYY;
        for (int i = tid; i < 2560; i += 256) {
            int f = i >> 5, q = i & 31;
            *(float4*)&Ys[f * 128 + q * 4] =
                *(const float4*)(yb + (size_t)f * TYY + y0 + q * 4);
        }
        const float* xpb = g_xp + (size_t)b * NF * TXX;
        for (int i = tid; i < 2560; i += 256) {
            int f = i >> 5, q = i & 31;
            *(float4*)&Xs[f * 128 + q * 4] =
                *(const float4*)(xpb + (size_t)f * TXX + t0 + q * 4);
        }
        __syncthreads();

        int tx = tid & 15;
        int ty = tid >> 4;

        unsigned long long acc2[8][4];
#pragma unroll
        for (int i = 0; i < 8; ++i)
#pragma unroll
            for (int j = 0; j < 4; ++j) acc2[i][j] = 0ull;

#pragma unroll 4
        for (int f = 0; f < NF; ++f) {
            float4 ya = *(const float4*)&Ys[f * 128 + ty * 8];
            float4 yb4 = *(const float4*)&Ys[f * 128 + ty * 8 + 4];
            float4 xa = *(const float4*)&Xs[f * 128 + tx * 8];
            float4 xb4 = *(const float4*)&Xs[f * 128 + tx * 8 + 4];
            unsigned long long xp0, xp1, xp2, xp3;
            asm("mov.b64 %0,{%1,%2};" : "=l"(xp0) : "f"(xa.x),  "f"(xa.y));
            asm("mov.b64 %0,{%1,%2};" : "=l"(xp1) : "f"(xa.z),  "f"(xa.w));
            asm("mov.b64 %0,{%1,%2};" : "=l"(xp2) : "f"(xb4.x), "f"(xb4.y));
            asm("mov.b64 %0,{%1,%2};" : "=l"(xp3) : "f"(xb4.z), "f"(xb4.w));
            float yv[8] = {ya.x, ya.y, ya.z, ya.w, yb4.x, yb4.y, yb4.z, yb4.w};
#pragma unroll
            for (int i = 0; i < 8; ++i) {
                unsigned long long yd;
                asm("mov.b64 %0,{%1,%1};" : "=l"(yd) : "f"(yv[i]));
                asm("fma.rn.f32x2 %0,%1,%2,%0;" : "+l"(acc2[i][0]) : "l"(yd), "l"(xp0));
                asm("fma.rn.f32x2 %0,%1,%2,%0;" : "+l"(acc2[i][1]) : "l"(yd), "l"(xp1));
                asm("fma.rn.f32x2 %0,%1,%2,%0;" : "+l"(acc2[i][2]) : "l"(yd), "l"(xp2));
                asm("fma.rn.f32x2 %0,%1,%2,%0;" : "+l"(acc2[i][3]) : "l"(yd), "l"(xp3));
            }
        }

        int tbase = t0 + tx * 8;
        float xsqv[8];
#pragma unroll
        for (int j = 0; j < 8; ++j) xsqv[j] = g_xsq[b * TXX + tbase + j];

#pragma unroll
        for (int i = 0; i < 8; ++i) {
            int yg = y0 + ty * 8 + i;
            if (yg >= ylen) continue;
            float ysv = g_ysq[b * TYY + yg];
            float av[8];
#pragma unroll
            for (int j2 = 0; j2 < 4; ++j2) {
                float lo, hi;
                asm("mov.b64 {%0,%1}, %2;" : "=f"(lo), "=f"(hi) : "l"(acc2[i][j2]));
                av[j2 * 2] = lo; av[j2 * 2 + 1] = hi;
            }
            float ov[8];
#pragma unroll
            for (int j = 0; j < 8; ++j) {
                float val = ((ysv + av[j]) + xsqv[j]) + CONSTF;
                ov[j] = (tbase + j < xlen) ? val : NEGF;
            }
            float* vout = g_v + ((size_t)b * TYY + yg) * TXX + tbase;
            *(float4*)(vout + 0) = make_float4(ov[0], ov[1], ov[2], ov[3]);
            *(float4*)(vout + 4) = make_float4(ov[4], ov[5], ov[6], ov[7]);
        }
        __syncthreads();
        if (tid == 0) {
            __threadfence();
            atomicAdd(&g_cnt[b * NYT + yi], 1);
        }
        return;
    }

    // ================= dp consumer (R8 single-warp + band gating) =========
    if (threadIdx.x >= 32) return;
    float* ring = sm;                                        // [DSLOT][TXX]
    unsigned short* sdec = (unsigned short*)(sm + DSLOT * TXX); // [TYY+8][32]

    int b = blockIdx.x;
    int lane = threadIdx.x;
    int ylen = yl[b], xlen = xl[b];

    const float* vb = g_v + (size_t)b * TYY * TXX;
    uint32_t ring_base = (uint32_t)__cvta_generic_to_shared(ring);
    uint32_t mbar_addr = ring_base + MBAR_OFF;

    if (lane == 0) {
#pragma unroll
        for (int m = 0; m < 4; ++m)
            asm volatile("mbarrier.init.shared.b64 [%0], 1;"
                         :: "r"(mbar_addr + m * 8) : "memory");
    }
    __syncwarp();
    asm volatile("fence.proxy.async.shared::cta;" ::: "memory");

    const volatile int* cp = (const volatile int*)&g_cnt[b * NYT];
    int gated = -1;   // highest band confirmed complete

#define DP_GATE(bi_)                                                           \
    do {                                                                       \
        int row_ = (bi_) * 8;                                                  \
        if (row_ < ylen) {                                                     \
            int band_ = row_ >> 7;                                             \
            if (band_ > gated) {                                               \
                int exp_ = 2 + ((band_ >= 1 && xlen > 256) ? 1 : 0);           \
                while (cp[band_] < exp_) { }                                   \
                __threadfence();                                               \
                gated = band_;                                                 \
            }                                                                  \
        }                                                                      \
    } while (0)

#define DP_ISSUE(bi_)                                                          \
    do {                                                                       \
        if (lane == 0) {                                                       \
            int r0_ = (bi_) * 8;                                               \
            if (r0_ + 8 > TYY) r0_ = TYY - 8;                                  \
            uint32_t mb_ = mbar_addr + ((bi_) & 3) * 8;                        \
            uint32_t dst_ = ring_base + (uint32_t)(((bi_) & 3) * BLK_BYTES);   \
            const float* src_ = vb + (size_t)r0_ * TXX;                        \
            asm volatile("mbarrier.arrive.expect_tx.shared.b64 _, [%0], %1;"   \
                         :: "r"(mb_), "r"((uint32_t)BLK_BYTES) : "memory");    \
            asm volatile(                                                      \
                "cp.async.bulk.shared::cta.global.mbarrier::complete_tx::bytes"\
                " [%0], [%1], %2, [%3];"                                       \
                :: "r"(dst_), "l"(src_), "r"((uint32_t)BLK_BYTES), "r"(mb_)    \
                : "memory");                                                   \
        }                                                                      \
    } while (0)

#define DP_WAIT(bi_)                                                           \
    do {                                                                       \
        uint32_t mb_ = mbar_addr + ((bi_) & 3) * 8;                            \
        uint32_t par_ = (uint32_t)(((bi_) >> 2) & 1);                          \
        while (!mbar_try_wait(mb_, par_)) { }                                  \
    } while (0)

    DP_GATE(0); DP_ISSUE(0);
    DP_GATE(1); DP_ISSUE(1);

    float q[12];
#pragma unroll
    for (int j = 0; j < 12; ++j) q[j] = NEGF;
    if (lane == 0) q[0] = 0.0f;

    for (int yb2 = 0; yb2 < ylen; yb2 += 8) {
        int bi = yb2 >> 3;
        DP_GATE(bi + 2);
        DP_ISSUE(bi + 2);
        DP_WAIT(bi);

#pragma unroll
        for (int h = 0; h < 2; ++h) {
            float4 r0[4], r1[4], r2[4];
#pragma unroll
            for (int k = 0; k < 4; ++k) {
                const float4* rp = (const float4*)(ring +
                    ((yb2 + h * 4 + k) & (DSLOT - 1)) * TXX + lane * 12);
                r0[k] = rp[0]; r1[k] = rp[1]; r2[k] = rp[2];
            }
#pragma unroll
            for (int k = 0; k < 4; ++k) {
                int yy = yb2 + h * 4 + k;
                float carry = __shfl_up_sync(0xffffffffu, q[11], 1);
                if (lane == 0) carry = NEGF;
                float vv[12] = {r0[k].x, r0[k].y, r0[k].z, r0[k].w,
                                r1[k].x, r1[k].y, r1[k].z, r1[k].w,
                                r2[k].x, r2[k].y, r2[k].z, r2[k].w};
                unsigned bits = 0u;
#pragma unroll
                for (int j = 11; j >= 1; --j)
                    bits |= ((q[j] < q[j - 1]) ? 1u : 0u) << j;
                bits |= (q[0] < carry) ? 1u : 0u;
#pragma unroll
                for (int j = 11; j >= 1; --j)
                    q[j] = vv[j] + fmaxf(q[j], q[j - 1]);
                q[0] = vv[0] + fmaxf(q[0], carry);
                sdec[yy * 32 + lane] = (unsigned short)bits;
            }
        }
    }
    {
        int bl = (ylen - 1) >> 3;
        DP_WAIT(bl + 1);
        DP_WAIT(bl + 2);
    }
    __syncwarp();

#pragma unroll
    for (int j = 0; j < 12; ++j) g_dur[b * TXX + lane * 12 + j] = 0.0f;
    __syncwarp();

    if (lane == 0) {
        int idx = xlen - 1;
        int w = idx / 12, r = idx - w * 12;
        int cnt = 0;
        int* gi = g_idx + b * TYY;
        int yy = ylen - 1;
        while (yy >= 0) {
            int w0 = w;
            unsigned wa[8], wb2[8];
            if (yy >= 7) {
#pragma unroll
                for (int k = 0; k < 8; ++k)
                    wa[k] = (unsigned)sdec[(yy - k) * 32 + w0];
                if (w0 > 0) {
#pragma unroll
                    for (int k = 0; k < 8; ++k)
                        wb2[k] = (unsigned)sdec[(yy - k) * 32 + (w0 - 1)];
                } else {
#pragma unroll
                    for (int k = 0; k < 8; ++k) wb2[k] = 0u;
                }
#pragma unroll
                for (int k = 0; k < 8; ++k) {
                    int row = yy - k;
                    unsigned use = (w == w0) ? wa[k] : wb2[k];
                    gi[row] = idx;
                    cnt++;
                    bool move = (idx != 0) && (row > 0) &&
                                ((idx == row) || (((use >> r) & 1u) != 0u));
                    if (move) {
                        g_dur[b * TXX + idx] = (float)cnt;
                        cnt = 0; idx--;
                        if (--r < 0) { r = 11; w--; }
                    }
                }
                yy -= 8;
            } else {
                int row = yy;
                unsigned use = (unsigned)sdec[row * 32 + w];
                gi[row] = idx;
                cnt++;
                bool move = (idx != 0) && (row > 0) &&
                            ((idx == row) || (((use >> r) & 1u) != 0u));
                if (move) {
                    g_dur[b * TXX + idx] = (float)cnt;
                    cnt = 0; idx--;
                    if (--r < 0) { r = 11; w--; }
                }
                yy -= 1;
            }
        }
        g_dur[b * TXX + idx] = (float)cnt;
    }
}

// ---------------------------------------------------------------------------
// attn[b][t][s] = (s < ylen && g_idx[b][s] == t) ? 1 : 0
__global__ __launch_bounds__(128) void attn_kernel(const int* __restrict__ yl,
                                                   float* __restrict__ out) {
    int b = blockIdx.y;
    int t = blockIdx.x;
    int tid = threadIdx.x;
    int ylen = yl[b];
    const int* gi = g_idx + b * TYY;
    float* o = out + ((size_t)b * TXX + t) * TYY;
#pragma unroll
    for (int it = 0; it < 3; ++it) {
        int s4 = tid + it * 128;
        int s = s4 * 4;
        int4 iv = *(const int4*)(gi + s);
        float4 ov;
        ov.x = (s + 0 < ylen && iv.x == t) ? 1.f : 0.f;
        ov.y = (s + 1 < ylen && iv.y == t) ? 1.f : 0.f;
        ov.z = (s + 2 < ylen && iv.z == t) ? 1.f : 0.f;
        ov.w = (s + 3 < ylen && iv.w == t) ? 1.f : 0.f;
        *(float4*)(o + s) = ov;
    }
}

// ---------------------------------------------------------------------------
// loss + durations tail
__global__ __launch_bounds__(256) void loss_kernel(const float* __restrict__ pred,
                                                   const int* __restrict__ xl,
                                                   float* __restrict__ out,
                                                   int write_tail) {
    __shared__ float red[256];
    int tid = threadIdx.x;
    float s = 0.f;
    for (int i = tid; i < BB * TXX; i += 256) {
        int b = i / TXX, t = i - b * TXX;
        float dur = g_dur[i];
        float tl = (t < xl[b]) ? logf(dur + 1e-8f) : 0.0f;
        float d = pred[i] - tl;
        s += d * d;
        if (write_tail) out[ATTN_SZ + 1 + i] = dur;
    }
    red[tid] = s;
    __syncthreads();
    for (int off = 128; off > 0; off >>= 1) {
        if (tid < off) red[tid] += red[tid + off];
        __syncthreads();
    }
    if (tid == 0 && write_tail) {
        int sx = 0;
        for (int bb2 = 0; bb2 < BB; ++bb2) sx += xl[bb2];
        out[ATTN_SZ] = red[0] / (float)sx;
    }
}

// ---------------------------------------------------------------------------
extern "C" void kernel_launch(void* const* d_in, const int* in_sizes, int n_in,
                              void* d_out, int out_size) {
    const float* x    = (const float*)d_in[0];
    const float* y    = (const float*)d_in[1];
    const int*   xlen = (const int*)d_in[4];
    const int*   ylen = (const int*)d_in[5];
    const float* pred = (const float*)d_in[6];
    const float* W    = (const float*)d_in[7];
    const float* bias = (const float*)d_in[8];
    float* out = (float*)d_out;

    cudaFuncSetAttribute(fused_kernel, cudaFuncAttributeMaxDynamicSharedMemorySize,
                         DP_SMEM);

    ysq_kernel<<<dim3(TYY / 256, BB), 256>>>(y);
    xp_kernel<<<dim3(TXX / 128, BB), 160>>>(x, W, bias);
    fused_kernel<<<BB + NCROSS, 256, DP_SMEM>>>(y, xlen, ylen);
    attn_kernel<<<dim3(TXX, BB), 128>>>(ylen, out);

    int write_tail = ((size_t)out_size >= ATTN_SZ + 1 + BB * TXX) ? 1 : 0;
    loss_kernel<<<1, 256>>>(pred, xlen, out, write_tail);
}